// round 13
// baseline (speedup 1.0000x reference)
#include <cuda_runtime.h>
#include <cstddef>
#include <cstdint>

#define B_ 512
#define T_ 1024
#define U_ 128
#define RSTR 160   // h row stride in floats (640B = 5*128B: rows stay 128B-aligned)

typedef unsigned long long ull;
typedef unsigned int uint;

// Allocation-free scratch (device global, .bss)
__device__ float g_pbuf[(size_t)T_ * B_ * U_];  // px1

// ---------- packed f32x2 helpers (Blackwell, PTX-only) ----------
__device__ __forceinline__ ull bc2(float v) {
    ull r; asm("mov.b64 %0, {%1,%1};" : "=l"(r) : "f"(v)); return r;
}
__device__ __forceinline__ ull pack2(float a, float b) {
    ull r; asm("mov.b64 %0, {%1,%2};" : "=l"(r) : "f"(a), "f"(b)); return r;
}
__device__ __forceinline__ void fma2(ull& d, ull a, ull b) {
    asm("fma.rn.f32x2 %0, %1, %2, %0;" : "+l"(d) : "l"(a), "l"(b));
}
__device__ __forceinline__ ull add2(ull a, ull b) {
    ull r; asm("add.rn.f32x2 %0, %1, %2;" : "=l"(r) : "l"(a), "l"(b)); return r;
}
__device__ __forceinline__ void unpk(ull v, float& lo, float& hi) {
    asm("mov.b64 {%0,%1}, %2;" : "=f"(lo), "=f"(hi) : "l"(v));
}

// symmetric packed butterfly over the 4 sub lanes (NO selects):
// after this, every lane holds the full 4-slice sum (still k-pair packed).
__device__ __forceinline__ ull bfly4(ull v) {
    uint lo = (uint)v, hi = (uint)(v >> 32);
    uint plo = __shfl_xor_sync(0xffffffffu, lo, 1);
    uint phi = __shfl_xor_sync(0xffffffffu, hi, 1);
    ull a = pack2(__uint_as_float(lo) + __uint_as_float(plo) * 0.f, 0.f); // placeholder unused
    // do it properly in packed domain:
    ull p1; asm("mov.b64 %0, {%1,%2};" : "=l"(p1) : "r"(plo), "r"(phi));
    ull s1 = add2(v, p1);
    uint lo2 = (uint)s1, hi2 = (uint)(s1 >> 32);
    uint qlo = __shfl_xor_sync(0xffffffffu, lo2, 2);
    uint qhi = __shfl_xor_sync(0xffffffffu, hi2, 2);
    ull p2; asm("mov.b64 %0, {%1,%2};" : "=l"(p2) : "r"(qlo), "r"(qhi));
    (void)a;
    return add2(s1, p2);
}

// h layout for 4 slices: k = sub*32 + i*4 + m -> phys = i*16 + sub*4 + m.
// A warp's four sub-chunks sit in one 64B span -> every LDS.128 = 1 wavefront.
__device__ __forceinline__ int hphys(int k) {
    return ((k >> 2) & 7) * 16 + (k >> 5) * 4 + (k & 3);
}

// ============================================================================
// Parallel GEMM + bias (known-good since R4; occupancy bumped 2 -> 3)
// ============================================================================
template <int KD, bool XLAY>
__global__ __launch_bounds__(256, 3)
void gemm_bias(const float* __restrict__ A, const float* __restrict__ W,
               const float* __restrict__ bias, float* __restrict__ out)
{
    extern __shared__ float sm[];
    float* Ws = sm;               // [KD][128]
    float* As = sm + KD * U_;     // [KD][68]
    const int tid  = threadIdx.x;
    const int row0 = blockIdx.x * 64;

    for (int i = tid; i < KD * U_; i += 256) Ws[i] = W[i];

    for (int i = tid; i < 64 * KD; i += 256) {
        int r = i / KD, k = i - r * KD;
        size_t off;
        if (XLAY) {
            int t = row0 >> 9;
            int b = (row0 & (B_ - 1)) + r;
            off = ((size_t)b * T_ + t) * KD + k;
        } else {
            off = (size_t)(row0 + r) * KD + k;
        }
        As[k * 68 + r] = A[off];
    }
    __syncthreads();

    const int u0 = (tid & 31) * 4;
    const int rb = (tid >> 5) * 8;

    ull acc[4][4];
#pragma unroll
    for (int a = 0; a < 4; a++)
#pragma unroll
        for (int b = 0; b < 4; b++) acc[a][b] = 0ULL;

#pragma unroll 4
    for (int k = 0; k < KD; k++) {
        ulonglong2 a01 = *(const ulonglong2*)(As + k * 68 + rb);
        ulonglong2 a23 = *(const ulonglong2*)(As + k * 68 + rb + 4);
        float4 w4 = *(const float4*)(Ws + k * U_ + u0);
        ull w;
        w = bc2(w4.x);
        fma2(acc[0][0], a01.x, w); fma2(acc[0][1], a01.y, w);
        fma2(acc[0][2], a23.x, w); fma2(acc[0][3], a23.y, w);
        w = bc2(w4.y);
        fma2(acc[1][0], a01.x, w); fma2(acc[1][1], a01.y, w);
        fma2(acc[1][2], a23.x, w); fma2(acc[1][3], a23.y, w);
        w = bc2(w4.z);
        fma2(acc[2][0], a01.x, w); fma2(acc[2][1], a01.y, w);
        fma2(acc[2][2], a23.x, w); fma2(acc[2][3], a23.y, w);
        w = bc2(w4.w);
        fma2(acc[3][0], a01.x, w); fma2(acc[3][1], a01.y, w);
        fma2(acc[3][2], a23.x, w); fma2(acc[3][3], a23.y, w);
    }

    float f[4][8];
#pragma unroll
    for (int uu = 0; uu < 4; uu++)
#pragma unroll
        for (int rp = 0; rp < 4; rp++) unpk(acc[uu][rp], f[uu][2 * rp], f[uu][2 * rp + 1]);

    float4 bv = *(const float4*)(bias + u0);
#pragma unroll
    for (int rr = 0; rr < 8; rr++) {
        float4 o = make_float4(f[0][rr] + bv.x, f[1][rr] + bv.y,
                               f[2][rr] + bv.z, f[3][rr] + bv.w);
        *(float4*)(out + (size_t)(row0 + rb + rr) * U_ + u0) = o;
    }
}

// ============================================================================
// recurBCD5: fully fused B+C+D. 512 threads = 128 units x 4 k-slices
// (4 warps/SMSP; 48 ull weights/thread -> ~150 regs -> deep MLP headroom).
// Per iter t:
//   h1_t     = relu(p1_t + h1_{t-1}@Wh1)
//   h2_{t-1} = relu(h1_{t-1}@Wx2 + b2 + h2_{t-2}@Wh2)   (shared accumulator)
// Fold: symmetric packed butterfly (xor1, xor2), zero selects; afterwards all
// lanes hold all 4 rows' sums -> thread sub owns row sub; epilogue on ALL 512.
// ============================================================================
__global__ __launch_bounds__(512, 1)
void recurBCD5(const float* __restrict__ p,
               const float* __restrict__ Wh1c, const float* __restrict__ Wx2c,
               const float* __restrict__ b2c,  const float* __restrict__ Wh2c,
               const float* __restrict__ Wdc,  const float* __restrict__ bdc,
               float* __restrict__ dout)
{
    __shared__ __align__(16) float h1s[2][4 * RSTR];
    __shared__ __align__(16) float h2s[2][4 * RSTR];
    __shared__ float part_s[4 * U_];

    const int tid = threadIdx.x;
    const int u   = tid >> 2;          // unit 0..127
    const int sub = tid & 3;           // k-slice 0..3 (adjacent lanes)
    const int r0  = blockIdx.x * 4;

    // 16 packed k-pair weights per matrix for k = sub*32 .. sub*32+31
    ull wp[16], wq[16], wv[16];
#pragma unroll
    for (int j = 0; j < 16; j++) {
        int k = sub * 32 + 2 * j;
        wp[j] = pack2(Wh1c[(size_t)k * U_ + u], Wh1c[(size_t)(k + 1) * U_ + u]);
        wq[j] = pack2(Wx2c[(size_t)k * U_ + u], Wx2c[(size_t)(k + 1) * U_ + u]);
        wv[j] = pack2(Wh2c[(size_t)k * U_ + u], Wh2c[(size_t)(k + 1) * U_ + u]);
    }
    const float b2v = b2c[u];

    for (int i = tid; i < 4 * RSTR; i += 512) {
        h1s[0][i] = 0.f; h1s[1][i] = 0.f;
        h2s[0][i] = 0.f; h2s[1][i] = 0.f;
    }

    const int physu = hphys(u);
    // owned (row sub, unit u) stream of p
    const float* pown = p + ((size_t)(r0 + sub)) * U_ + u;
    float pv = pown[0];
    float hfin = 0.f;                  // final h2(row sub, unit u)
    __syncthreads();

    for (int t = 0; t <= T_; t++) {
        int tn = (t < T_ - 1) ? t + 1 : T_ - 1;
        float pnext = pown[(size_t)tn * B_ * U_];

        const float* hb1 = h1s[t & 1];        // h1_{t-1}
        float*       hn1 = h1s[(t + 1) & 1];
        const float* hb2 = h2s[t & 1];        // h2_{t-2}
        float*       hn2 = h2s[(t + 1) & 1];

        ull acc[4] = {0ULL, 0ULL, 0ULL, 0ULL};   // Wh1 @ h1
        ull bcc[4] = {0ULL, 0ULL, 0ULL, 0ULL};   // Wx2 @ h1 + Wh2 @ h2
#pragma unroll
        for (int r = 0; r < 4; r++) {
            const float* rb1 = hb1 + r * RSTR + sub * 4;
            const float* rb2 = hb2 + r * RSTR + sub * 4;
#pragma unroll
            for (int i = 0; i < 8; i++) {
                ulonglong2 hv = *(const ulonglong2*)(rb1 + i * 16);
                fma2(acc[r], hv.x, wp[2 * i]);
                fma2(acc[r], hv.y, wp[2 * i + 1]);
                fma2(bcc[r], hv.x, wq[2 * i]);
                fma2(bcc[r], hv.y, wq[2 * i + 1]);
                ulonglong2 gv = *(const ulonglong2*)(rb2 + i * 16);
                fma2(bcc[r], gv.x, wv[2 * i]);
                fma2(bcc[r], gv.y, wv[2 * i + 1]);
            }
        }

        // symmetric butterfly: all lanes end with complete slice-sums
        float s1[4], s2[4];
#pragma unroll
        for (int r = 0; r < 4; r++) {
            ull fa = bfly4(acc[r]);
            float alo, ahi; unpk(fa, alo, ahi);
            s1[r] = alo + ahi;
            ull fb = bfly4(bcc[r]);
            float blo, bhi; unpk(fb, blo, bhi);
            s2[r] = blo + bhi;
        }

        // distributed epilogue: thread handles row = sub
        if (t >= 1) {                          // h2_{t-1}
            hfin = fmaxf(s2[sub] + b2v, 0.f);
            hn2[sub * RSTR + physu] = hfin;
        }
        if (t < T_) {                          // h1_t
            hn1[sub * RSTR + physu] = fmaxf(s1[sub] + pv, 0.f);
            pv = pnext;
        }
        __syncthreads();
    }

    // final projection: thread (u,sub) owns h2_{T-1}(row sub, unit u) in hfin
    part_s[sub * U_ + u] = hfin * Wdc[u];
    __syncthreads();
    const int wid = tid >> 5, lid = tid & 31;
    if (wid < 4) {
        const float* pr = part_s + wid * U_;
        float a = pr[lid] + pr[lid + 32] + pr[lid + 64] + pr[lid + 96];
#pragma unroll
        for (int m = 16; m > 0; m >>= 1)
            a += __shfl_xor_sync(0xffffffffu, a, m);
        if (lid == 0) dout[r0 + wid] = a + bdc[0];
    }
}

// ============================================================================
extern "C" void kernel_launch(void* const* d_in, const int* in_sizes, int n_in,
                              void* d_out, int out_size)
{
    (void)in_sizes; (void)n_in; (void)out_size;
    const float* x   = (const float*)d_in[0];
    const float* Wx1 = (const float*)d_in[1];
    const float* Wh1 = (const float*)d_in[2];
    const float* b1  = (const float*)d_in[3];
    const float* Wx2 = (const float*)d_in[4];
    const float* Wh2 = (const float*)d_in[5];
    const float* b2  = (const float*)d_in[6];
    const float* Wd  = (const float*)d_in[7];
    const float* bd  = (const float*)d_in[8];
    float* out = (float*)d_out;

    float* pbuf;
    cudaGetSymbolAddress((void**)&pbuf, g_pbuf);

    const int ngrid = (T_ * B_) / 64;                        // 8192 tiles
    const int smemA = (64 * U_ + 64 * 68) * sizeof(float);   // 50176 B
    cudaFuncSetAttribute(gemm_bias<64, true>,
                         cudaFuncAttributeMaxDynamicSharedMemorySize, smemA);

    // Phase A: px1 = x @ Wx1 + b1           (layout [t][b][u])
    gemm_bias<64, true><<<ngrid, 256, smemA>>>(x, Wx1, b1, pbuf);
    // Phases B+C+D fully fused
    recurBCD5<<<B_ / 4, 512>>>(pbuf, Wh1, Wx2, b2, Wh2, Wd, bd, out);
}

// round 14
// speedup vs baseline: 1.1833x; 1.1833x over previous
#include <cuda_runtime.h>
#include <cstddef>
#include <cstdint>

#define B_ 512
#define T_ 1024
#define U_ 128
#define RSTR 132   // h row stride in floats (16B-aligned rows)

typedef unsigned long long ull;
typedef unsigned int uint;

// Allocation-free scratch (device global, .bss)
__device__ float g_pbuf[(size_t)T_ * B_ * U_];  // px1

// ---------- packed f32x2 helpers (Blackwell, PTX-only) ----------
__device__ __forceinline__ ull bc2(float v) {
    ull r; asm("mov.b64 %0, {%1,%1};" : "=l"(r) : "f"(v)); return r;
}
__device__ __forceinline__ ull pack2(float a, float b) {
    ull r; asm("mov.b64 %0, {%1,%2};" : "=l"(r) : "f"(a), "f"(b)); return r;
}
__device__ __forceinline__ void fma2(ull& d, ull a, ull b) {
    asm("fma.rn.f32x2 %0, %1, %2, %0;" : "+l"(d) : "l"(a), "l"(b));
}
__device__ __forceinline__ ull add2(ull a, ull b) {
    ull r; asm("add.rn.f32x2 %0, %1, %2;" : "=l"(r) : "l"(a), "l"(b)); return r;
}
__device__ __forceinline__ void unpk(ull v, float& lo, float& hi) {
    asm("mov.b64 {%0,%1}, %2;" : "=f"(lo), "=f"(hi) : "l"(v));
}

// ============================================================================
// Parallel GEMM + bias (known-good since R4)
// ============================================================================
template <int KD, bool XLAY>
__global__ __launch_bounds__(256, 3)
void gemm_bias(const float* __restrict__ A, const float* __restrict__ W,
               const float* __restrict__ bias, float* __restrict__ out)
{
    extern __shared__ float sm[];
    float* Ws = sm;               // [KD][128]
    float* As = sm + KD * U_;     // [KD][68]
    const int tid  = threadIdx.x;
    const int row0 = blockIdx.x * 64;

    for (int i = tid; i < KD * U_; i += 256) Ws[i] = W[i];

    for (int i = tid; i < 64 * KD; i += 256) {
        int r = i / KD, k = i - r * KD;
        size_t off;
        if (XLAY) {
            int t = row0 >> 9;
            int b = (row0 & (B_ - 1)) + r;
            off = ((size_t)b * T_ + t) * KD + k;
        } else {
            off = (size_t)(row0 + r) * KD + k;
        }
        As[k * 68 + r] = A[off];
    }
    __syncthreads();

    const int u0 = (tid & 31) * 4;
    const int rb = (tid >> 5) * 8;

    ull acc[4][4];
#pragma unroll
    for (int a = 0; a < 4; a++)
#pragma unroll
        for (int b = 0; b < 4; b++) acc[a][b] = 0ULL;

#pragma unroll 4
    for (int k = 0; k < KD; k++) {
        ulonglong2 a01 = *(const ulonglong2*)(As + k * 68 + rb);
        ulonglong2 a23 = *(const ulonglong2*)(As + k * 68 + rb + 4);
        float4 w4 = *(const float4*)(Ws + k * U_ + u0);
        ull w;
        w = bc2(w4.x);
        fma2(acc[0][0], a01.x, w); fma2(acc[0][1], a01.y, w);
        fma2(acc[0][2], a23.x, w); fma2(acc[0][3], a23.y, w);
        w = bc2(w4.y);
        fma2(acc[1][0], a01.x, w); fma2(acc[1][1], a01.y, w);
        fma2(acc[1][2], a23.x, w); fma2(acc[1][3], a23.y, w);
        w = bc2(w4.z);
        fma2(acc[2][0], a01.x, w); fma2(acc[2][1], a01.y, w);
        fma2(acc[2][2], a23.x, w); fma2(acc[2][3], a23.y, w);
        w = bc2(w4.w);
        fma2(acc[3][0], a01.x, w); fma2(acc[3][1], a01.y, w);
        fma2(acc[3][2], a23.x, w); fma2(acc[3][3], a23.y, w);
    }

    float f[4][8];
#pragma unroll
    for (int uu = 0; uu < 4; uu++)
#pragma unroll
        for (int rp = 0; rp < 4; rp++) unpk(acc[uu][rp], f[uu][2 * rp], f[uu][2 * rp + 1]);

    float4 bv = *(const float4*)(bias + u0);
#pragma unroll
    for (int rr = 0; rr < 8; rr++) {
        float4 o = make_float4(f[0][rr] + bv.x, f[1][rr] + bv.y,
                               f[2][rr] + bv.z, f[3][rr] + bv.w);
        *(float4*)(out + (size_t)(row0 + rb + rr) * U_ + u0) = o;
    }
}

// ============================================================================
// recurWS: warp-specialized fused B+C+D. 384 threads = 3 warp-groups of 128
// (exactly 3 warps/SMSP — below the nw>=4 smem-crossbar bind). Thread = unit,
// full k-range, ONE matrix per WG (64 ull = 128 regs), NO shuffles/folds.
//   WG0 at t (t<T):        h1_t     = relu(p_t + Wh1@h1_{t-1})   -> h1s
//   WG1 at t (1<=t<=T):    part[t&1]= Wx2@h1_{t-1}               (raw)
//   WG2 at t (2<=t<=T+1):  h2_{t-2} = relu(part[(t-1)&1] + Wh2@h2_{t-3} + b2)
// h2 lags two steps -> ONE barrier per step. Loop t = 0..T+1.
// ============================================================================
__global__ __launch_bounds__(384, 1)
void recurWS(const float* __restrict__ p,
             const float* __restrict__ Wh1c, const float* __restrict__ Wx2c,
             const float* __restrict__ b2c,  const float* __restrict__ Wh2c,
             const float* __restrict__ Wdc,  const float* __restrict__ bdc,
             float* __restrict__ dout)
{
    __shared__ __align__(16) float h1s[2][4 * RSTR];
    __shared__ __align__(16) float h2s[2][4 * RSTR];
    __shared__ float part[2][4 * U_];

    const int tid = threadIdx.x;
    const int wg  = tid >> 7;          // 0,1,2 (warps 0-3 / 4-7 / 8-11)
    const int u   = tid & 127;         // unit
    const int r0  = blockIdx.x * 4;

    // one weight matrix per WG, full k column for unit u: 64 packed pairs
    const float* Wsel = (wg == 0) ? Wh1c : (wg == 1) ? Wx2c : Wh2c;
    ull wp[64];
#pragma unroll
    for (int j = 0; j < 64; j++)
        wp[j] = pack2(Wsel[(size_t)(2 * j) * U_ + u],
                      Wsel[(size_t)(2 * j + 1) * U_ + u]);
    const float b2v = b2c[u];

    for (int i = tid; i < 4 * RSTR; i += 384) {
        h1s[0][i] = 0.f; h1s[1][i] = 0.f;
        h2s[0][i] = 0.f; h2s[1][i] = 0.f;
    }

    const float* prow = p + (size_t)r0 * U_ + u;
    float pv[4] = {0.f, 0.f, 0.f, 0.f};
    if (wg == 0) { pv[0] = prow[0]; pv[1] = prow[U_]; pv[2] = prow[2 * U_]; pv[3] = prow[3 * U_]; }
    float hfin[4] = {0.f, 0.f, 0.f, 0.f};
    __syncthreads();

    for (int t = 0; t <= T_ + 1; t++) {
        // prefetch next p one step ahead (WG0 only)
        float pn[4] = {0.f, 0.f, 0.f, 0.f};
        if (wg == 0 && t < T_ - 1) {
            const float* pp = prow + (size_t)(t + 1) * B_ * U_;
            pn[0] = pp[0]; pn[1] = pp[U_]; pn[2] = pp[2 * U_]; pn[3] = pp[3 * U_];
        }

        const float* hb = (wg == 2) ? h2s[t & 1] : h1s[t & 1];

        // full-k dot for 4 rows: 32 LDS.128 + 64 FFMA2 per row, 2 acc chains
        float s[4];
#pragma unroll
        for (int r = 0; r < 4; r++) {
            const float* rb = hb + r * RSTR;
            ull a0 = 0ULL, a1 = 0ULL;
#pragma unroll
            for (int c = 0; c < 32; c += 2) {
                ulonglong2 x0 = *(const ulonglong2*)(rb + 4 * c);
                fma2(a0, x0.x, wp[2 * c]);     fma2(a0, x0.y, wp[2 * c + 1]);
                ulonglong2 x1 = *(const ulonglong2*)(rb + 4 * c + 4);
                fma2(a1, x1.x, wp[2 * c + 2]); fma2(a1, x1.y, wp[2 * c + 3]);
            }
            float lo, hi; unpk(add2(a0, a1), lo, hi);
            s[r] = lo + hi;
        }

        if (wg == 0) {
            if (t < T_) {
                float* hn = h1s[(t + 1) & 1];
#pragma unroll
                for (int r = 0; r < 4; r++) {
                    hn[r * RSTR + u] = fmaxf(s[r] + pv[r], 0.f);
                    pv[r] = pn[r];
                }
            }
        } else if (wg == 1) {
            if (t >= 1 && t <= T_) {
                float* pt = part[t & 1];
#pragma unroll
                for (int r = 0; r < 4; r++) pt[r * U_ + u] = s[r];
            }
        } else {
            if (t >= 2) {
                const float* pt = part[(t - 1) & 1];
                float* hn = h2s[(t + 1) & 1];
#pragma unroll
                for (int r = 0; r < 4; r++) {
                    hfin[r] = fmaxf(s[r] + pt[r * U_ + u] + b2v, 0.f);
                    hn[r * RSTR + u] = hfin[r];
                }
            }
        }
        __syncthreads();
    }

    // final projection: WG2 holds h2_{T-1}(4 rows, unit u) in hfin
    if (wg == 2) {
        float wd = Wdc[u];
#pragma unroll
        for (int r = 0; r < 4; r++) part[0][r * U_ + u] = hfin[r] * wd;
    }
    __syncthreads();
    if (tid < 128) {
        int w = tid >> 5, lid = tid & 31;
        const float* pr = part[0] + w * U_;
        float a = pr[lid] + pr[lid + 32] + pr[lid + 64] + pr[lid + 96];
#pragma unroll
        for (int m = 16; m > 0; m >>= 1)
            a += __shfl_xor_sync(0xffffffffu, a, m);
        if (lid == 0) dout[r0 + w] = a + bdc[0];
    }
}

// ============================================================================
extern "C" void kernel_launch(void* const* d_in, const int* in_sizes, int n_in,
                              void* d_out, int out_size)
{
    (void)in_sizes; (void)n_in; (void)out_size;
    const float* x   = (const float*)d_in[0];
    const float* Wx1 = (const float*)d_in[1];
    const float* Wh1 = (const float*)d_in[2];
    const float* b1  = (const float*)d_in[3];
    const float* Wx2 = (const float*)d_in[4];
    const float* Wh2 = (const float*)d_in[5];
    const float* b2  = (const float*)d_in[6];
    const float* Wd  = (const float*)d_in[7];
    const float* bd  = (const float*)d_in[8];
    float* out = (float*)d_out;

    float* pbuf;
    cudaGetSymbolAddress((void**)&pbuf, g_pbuf);

    const int ngrid = (T_ * B_) / 64;                        // 8192 tiles
    const int smemA = (64 * U_ + 64 * 68) * sizeof(float);   // 50176 B
    cudaFuncSetAttribute(gemm_bias<64, true>,
                         cudaFuncAttributeMaxDynamicSharedMemorySize, smemA);

    // Phase A: px1 = x @ Wx1 + b1           (layout [t][b][u])
    gemm_bias<64, true><<<ngrid, 256, smemA>>>(x, Wx1, b1, pbuf);
    // Phases B+C+D fused, warp-specialized
    recurWS<<<B_ / 4, 384>>>(pbuf, Wh1, Wx2, b2, Wh2, Wd, bd, out);
}

// round 15
// speedup vs baseline: 1.6121x; 1.3624x over previous
#include <cuda_runtime.h>
#include <cstddef>
#include <cstdint>

#define B_ 512
#define T_ 1024
#define U_ 128
#define RSTR 144   // h row stride floats; r*576B keeps the 64B read-groups line-aligned

typedef unsigned long long ull;
typedef unsigned int uint;

// Allocation-free scratch (device global, .bss)
__device__ float g_pbuf[(size_t)T_ * B_ * U_];  // px1

// ---------- packed f32x2 helpers (Blackwell, PTX-only) ----------
__device__ __forceinline__ ull bc2(float v) {
    ull r; asm("mov.b64 %0, {%1,%1};" : "=l"(r) : "f"(v)); return r;
}
__device__ __forceinline__ ull pack2(float a, float b) {
    ull r; asm("mov.b64 %0, {%1,%2};" : "=l"(r) : "f"(a), "f"(b)); return r;
}
__device__ __forceinline__ void fma2(ull& d, ull a, ull b) {
    asm("fma.rn.f32x2 %0, %1, %2, %0;" : "+l"(d) : "l"(a), "l"(b));
}
__device__ __forceinline__ ull add2(ull a, ull b) {
    ull r; asm("add.rn.f32x2 %0, %1, %2;" : "=l"(r) : "l"(a), "l"(b)); return r;
}
__device__ __forceinline__ void unpk(ull v, float& lo, float& hi) {
    asm("mov.b64 {%0,%1}, %2;" : "=f"(lo), "=f"(hi) : "l"(v));
}

// symmetric 4-lane butterfly fold (xor1, xor2) in the packed domain, then
// collapse the k-pair: every lane returns the COMPLETE 4-slice sum. No SELs.
__device__ __forceinline__ float bfsum(ull v) {
    uint lo = (uint)v, hi = (uint)(v >> 32);
    uint plo = __shfl_xor_sync(0xffffffffu, lo, 1);
    uint phi = __shfl_xor_sync(0xffffffffu, hi, 1);
    ull p1; asm("mov.b64 %0, {%1,%2};" : "=l"(p1) : "r"(plo), "r"(phi));
    ull s1 = add2(v, p1);
    uint lo2 = (uint)s1, hi2 = (uint)(s1 >> 32);
    uint qlo = __shfl_xor_sync(0xffffffffu, lo2, 2);
    uint qhi = __shfl_xor_sync(0xffffffffu, hi2, 2);
    ull p2; asm("mov.b64 %0, {%1,%2};" : "=l"(p2) : "r"(qlo), "r"(qhi));
    ull s2 = add2(s1, p2);
    float a, b; unpk(s2, a, b);
    return a + b;
}

// h layout: k = sub*32 + i*4 + m  ->  phys = i*16 + sub*4 + m.
// A warp's four sub-chunks are adjacent 16B in one 64B span -> 64B useful/LDS.
__device__ __forceinline__ int hphys(int k) {
    return ((k >> 2) & 7) * 16 + (k >> 5) * 4 + (k & 3);
}

// ============================================================================
// Parallel GEMM + bias (known-good since R4)
// ============================================================================
template <int KD, bool XLAY>
__global__ __launch_bounds__(256, 3)
void gemm_bias(const float* __restrict__ A, const float* __restrict__ W,
               const float* __restrict__ bias, float* __restrict__ out)
{
    extern __shared__ float sm[];
    float* Ws = sm;               // [KD][128]
    float* As = sm + KD * U_;     // [KD][68]
    const int tid  = threadIdx.x;
    const int row0 = blockIdx.x * 64;

    for (int i = tid; i < KD * U_; i += 256) Ws[i] = W[i];

    for (int i = tid; i < 64 * KD; i += 256) {
        int r = i / KD, k = i - r * KD;
        size_t off;
        if (XLAY) {
            int t = row0 >> 9;
            int b = (row0 & (B_ - 1)) + r;
            off = ((size_t)b * T_ + t) * KD + k;
        } else {
            off = (size_t)(row0 + r) * KD + k;
        }
        As[k * 68 + r] = A[off];
    }
    __syncthreads();

    const int u0 = (tid & 31) * 4;
    const int rb = (tid >> 5) * 8;

    ull acc[4][4];
#pragma unroll
    for (int a = 0; a < 4; a++)
#pragma unroll
        for (int b = 0; b < 4; b++) acc[a][b] = 0ULL;

#pragma unroll 4
    for (int k = 0; k < KD; k++) {
        ulonglong2 a01 = *(const ulonglong2*)(As + k * 68 + rb);
        ulonglong2 a23 = *(const ulonglong2*)(As + k * 68 + rb + 4);
        float4 w4 = *(const float4*)(Ws + k * U_ + u0);
        ull w;
        w = bc2(w4.x);
        fma2(acc[0][0], a01.x, w); fma2(acc[0][1], a01.y, w);
        fma2(acc[0][2], a23.x, w); fma2(acc[0][3], a23.y, w);
        w = bc2(w4.y);
        fma2(acc[1][0], a01.x, w); fma2(acc[1][1], a01.y, w);
        fma2(acc[1][2], a23.x, w); fma2(acc[1][3], a23.y, w);
        w = bc2(w4.z);
        fma2(acc[2][0], a01.x, w); fma2(acc[2][1], a01.y, w);
        fma2(acc[2][2], a23.x, w); fma2(acc[2][3], a23.y, w);
        w = bc2(w4.w);
        fma2(acc[3][0], a01.x, w); fma2(acc[3][1], a01.y, w);
        fma2(acc[3][2], a23.x, w); fma2(acc[3][3], a23.y, w);
    }

    float f[4][8];
#pragma unroll
    for (int uu = 0; uu < 4; uu++)
#pragma unroll
        for (int rp = 0; rp < 4; rp++) unpk(acc[uu][rp], f[uu][2 * rp], f[uu][2 * rp + 1]);

    float4 bv = *(const float4*)(bias + u0);
#pragma unroll
    for (int rr = 0; rr < 8; rr++) {
        float4 o = make_float4(f[0][rr] + bv.x, f[1][rr] + bv.y,
                               f[2][rr] + bv.z, f[3][rr] + bv.w);
        *(float4*)(out + (size_t)(row0 + rb + rr) * U_ + u0) = o;
    }
}

// ============================================================================
// recurBCD6: fused B+C+D. 256 threads = 64 unit-pairs x 4 k-quarter slices
// (2 warps/SMSP). Each LDS.128 serves 4 distinct sub-chunks (64B useful) ->
// LDS/SMSP halves vs recurBCD (256 -> 128) at identical fma totals.
//   h1_t     = relu(p_t + Wh1@h1_{t-1})
//   h2_{t-1} = relu(Wx2@h1_{t-1} + Wh2@h2_{t-2} + b2)   (shared accumulator)
// Fold: symmetric bfly (no SELs); row ownership via unrolled predicated
// stores (sub == r), so no dynamic register indexing.
// ============================================================================
__global__ __launch_bounds__(256, 1)
void recurBCD6(const float* __restrict__ p,
               const float* __restrict__ Wh1c, const float* __restrict__ Wx2c,
               const float* __restrict__ b2c,  const float* __restrict__ Wh2c,
               const float* __restrict__ Wdc,  const float* __restrict__ bdc,
               float* __restrict__ dout)
{
    __shared__ __align__(16) float h1s[2][4 * RSTR];
    __shared__ __align__(16) float h2s[2][4 * RSTR];
    __shared__ float part_s[4 * U_];

    const int tid = threadIdx.x;
    const int u2  = tid >> 2;          // unit-pair 0..63
    const int sub = tid & 3;           // k-quarter slice (adjacent lanes)
    const int r0  = blockIdx.x * 4;
    const int ua  = 2 * u2, ub = ua + 1;

    // quarter-k packed weights for both units, all three matrices: 96 ull
    ull wpa[16], wpb[16], wqa[16], wqb[16], wva[16], wvb[16];
#pragma unroll
    for (int j = 0; j < 16; j++) {
        int k = sub * 32 + 2 * j;
        wpa[j] = pack2(Wh1c[(size_t)k * U_ + ua], Wh1c[(size_t)(k + 1) * U_ + ua]);
        wpb[j] = pack2(Wh1c[(size_t)k * U_ + ub], Wh1c[(size_t)(k + 1) * U_ + ub]);
        wqa[j] = pack2(Wx2c[(size_t)k * U_ + ua], Wx2c[(size_t)(k + 1) * U_ + ua]);
        wqb[j] = pack2(Wx2c[(size_t)k * U_ + ub], Wx2c[(size_t)(k + 1) * U_ + ub]);
        wva[j] = pack2(Wh2c[(size_t)k * U_ + ua], Wh2c[(size_t)(k + 1) * U_ + ua]);
        wvb[j] = pack2(Wh2c[(size_t)k * U_ + ub], Wh2c[(size_t)(k + 1) * U_ + ub]);
    }
    const float b2a = b2c[ua], b2b = b2c[ub];

    for (int i = tid; i < 4 * RSTR; i += 256) {
        h1s[0][i] = 0.f; h1s[1][i] = 0.f;
        h2s[0][i] = 0.f; h2s[1][i] = 0.f;
    }

    const int physua = hphys(ua);      // physub = physua + 1 (same i,s group)
    // owned p streams: (row r0+sub, units ua/ub); layout [t][b][u]
    const float* pa = p + ((size_t)(r0 + sub)) * U_ + ua;
    float pva = pa[0], pvb = pa[1];
    float hfa = 0.f, hfb = 0.f;        // final h2 (row sub, units ua/ub)
    __syncthreads();

    for (int t = 0; t <= T_; t++) {
        int tn = (t < T_ - 1) ? t + 1 : T_ - 1;
        float pna = pa[(size_t)tn * B_ * U_];
        float pnb = pa[(size_t)tn * B_ * U_ + 1];

        const float* hb1 = h1s[t & 1];        // h1_{t-1}
        float*       hn1 = h1s[(t + 1) & 1];
        const float* hb2 = h2s[t & 1];        // h2_{t-2}
        float*       hn2 = h2s[(t + 1) & 1];

        ull accA[4] = {0,0,0,0}, accB[4] = {0,0,0,0};   // Wh1 @ h1
        ull bccA[4] = {0,0,0,0}, bccB[4] = {0,0,0,0};   // Wx2@h1 + Wh2@h2
#pragma unroll
        for (int r = 0; r < 4; r++) {
            const float* rb1 = hb1 + r * RSTR + sub * 4;
            const float* rb2 = hb2 + r * RSTR + sub * 4;
#pragma unroll
            for (int i = 0; i < 8; i++) {
                ulonglong2 hv = *(const ulonglong2*)(rb1 + i * 16);
                fma2(accA[r], hv.x, wpa[2 * i]); fma2(accA[r], hv.y, wpa[2 * i + 1]);
                fma2(accB[r], hv.x, wpb[2 * i]); fma2(accB[r], hv.y, wpb[2 * i + 1]);
                fma2(bccA[r], hv.x, wqa[2 * i]); fma2(bccA[r], hv.y, wqa[2 * i + 1]);
                fma2(bccB[r], hv.x, wqb[2 * i]); fma2(bccB[r], hv.y, wqb[2 * i + 1]);
                ulonglong2 gv = *(const ulonglong2*)(rb2 + i * 16);
                fma2(bccA[r], gv.x, wva[2 * i]); fma2(bccA[r], gv.y, wva[2 * i + 1]);
                fma2(bccB[r], gv.x, wvb[2 * i]); fma2(bccB[r], gv.y, wvb[2 * i + 1]);
            }
        }

        // symmetric folds: every lane gets complete sums for all rows/units
        float s1a[4], s1b[4], s2a[4], s2b[4];
#pragma unroll
        for (int r = 0; r < 4; r++) {
            s1a[r] = bfsum(accA[r]);
            s1b[r] = bfsum(accB[r]);
            s2a[r] = bfsum(bccA[r]);
            s2b[r] = bfsum(bccB[r]);
        }

        // predicated ownership: lane sub handles row sub (no SELs, static idx)
        if (t >= 1) {
#pragma unroll
            for (int r = 0; r < 4; r++) if (sub == r) {
                hfa = fmaxf(s2a[r] + b2a, 0.f);
                hfb = fmaxf(s2b[r] + b2b, 0.f);
                *(float2*)(hn2 + r * RSTR + physua) = make_float2(hfa, hfb);
            }
        }
        if (t < T_) {
#pragma unroll
            for (int r = 0; r < 4; r++) if (sub == r) {
                float va = fmaxf(s1a[r] + pva, 0.f);
                float vb = fmaxf(s1b[r] + pvb, 0.f);
                *(float2*)(hn1 + r * RSTR + physua) = make_float2(va, vb);
            }
            pva = pna; pvb = pnb;
        }
        __syncthreads();
    }

    // final projection: lane (u2,sub) owns h2_{T-1}(row sub, units ua/ub)
#pragma unroll
    for (int r = 0; r < 4; r++) if (sub == r) {
        part_s[r * U_ + ua] = hfa * Wdc[ua];
        part_s[r * U_ + ub] = hfb * Wdc[ub];
    }
    __syncthreads();
    const int wid = tid >> 5, lid = tid & 31;
    if (wid < 4) {
        const float* pr = part_s + wid * U_;
        float a = pr[lid] + pr[lid + 32] + pr[lid + 64] + pr[lid + 96];
#pragma unroll
        for (int m = 16; m > 0; m >>= 1)
            a += __shfl_xor_sync(0xffffffffu, a, m);
        if (lid == 0) dout[r0 + wid] = a + bdc[0];
    }
}

// ============================================================================
extern "C" void kernel_launch(void* const* d_in, const int* in_sizes, int n_in,
                              void* d_out, int out_size)
{
    (void)in_sizes; (void)n_in; (void)out_size;
    const float* x   = (const float*)d_in[0];
    const float* Wx1 = (const float*)d_in[1];
    const float* Wh1 = (const float*)d_in[2];
    const float* b1  = (const float*)d_in[3];
    const float* Wx2 = (const float*)d_in[4];
    const float* Wh2 = (const float*)d_in[5];
    const float* b2  = (const float*)d_in[6];
    const float* Wd  = (const float*)d_in[7];
    const float* bd  = (const float*)d_in[8];
    float* out = (float*)d_out;

    float* pbuf;
    cudaGetSymbolAddress((void**)&pbuf, g_pbuf);

    const int ngrid = (T_ * B_) / 64;                        // 8192 tiles
    const int smemA = (64 * U_ + 64 * 68) * sizeof(float);   // 50176 B
    cudaFuncSetAttribute(gemm_bias<64, true>,
                         cudaFuncAttributeMaxDynamicSharedMemorySize, smemA);

    // Phase A: px1 = x @ Wx1 + b1           (layout [t][b][u])
    gemm_bias<64, true><<<ngrid, 256, smemA>>>(x, Wx1, b1, pbuf);
    // Phases B+C+D fused, 4-address divergent-LDS geometry
    recurBCD6<<<B_ / 4, 256>>>(pbuf, Wh1, Wx2, b2, Wh2, Wd, bd, out);
}